// round 15
// baseline (speedup 1.0000x reference)
#include <cuda_runtime.h>
#include <math.h>
#include <stdint.h>

#define BATCH 4
#define NN 4096
#define HID 128
#define G4 512
#define CAP 640
#define RS_CTAS 264
#define RS_THREADS 1024

typedef unsigned long long ull;

// ---------------- device scratch ----------------
__device__ float g_dinv[BATCH * NN];
__device__ int   g_cnt[BATCH * NN];
__device__ unsigned short g_idx[(size_t)BATCH * NN * CAP];   // ~21 MB
__device__ float g_zx[BATCH * HID * G4];                     // x-part of gates + biases
__device__ float g_lwm[BATCH * HID * HID];                   // lstm hidden [b][t][h]
__device__ float g_xs[(size_t)BATCH * NN * HID];             // d_j * x[b][j][:]
__device__ float g_agg[(size_t)BATCH * NN * HID];            // (A_norm @ x)[b][i][:]

__device__ __forceinline__ float sigf(float x) {
    return __fdividef(1.f, 1.f + __expf(-x));
}
__device__ __forceinline__ float tanh_fast(float x) {
    float e = __expf(2.f * x);
    return 1.f - __fdividef(2.f, e + 1.f);
}
__device__ __forceinline__ void fma2(ull& d, ull a, ull b) {
    asm("fma.rn.f32x2 %0, %1, %2, %0;" : "+l"(d) : "l"(a), "l"(b));
}
__device__ __forceinline__ float2 unpk(ull v) {
    float2 r; asm("mov.b64 {%0,%1}, %2;" : "=f"(r.x), "=f"(r.y) : "l"(v)); return r;
}
__device__ __forceinline__ ull pk(float x, float y) {
    ull r; asm("mov.b64 %0, {%1,%2};" : "=l"(r) : "f"(x), "f"(y)); return r;
}

// ---- degree + sparse index build + fused x-scale: persistent, 264 CTAs (2/SM) ----
__global__ void __launch_bounds__(RS_THREADS, 2) k_rowsum(const float* __restrict__ A,
                                                          const float* __restrict__ x) {
    int gwarp = (blockIdx.x * RS_THREADS + threadIdx.x) >> 5;
    int lane = threadIdx.x & 31;
    unsigned lt = (1u << lane) - 1u;
    const int nwarp = RS_CTAS * (RS_THREADS / 32);
    for (int row = gwarp; row < BATCH * NN; row += nwarp) {
        const float4* Ar = (const float4*)(A + (size_t)row * NN);
        unsigned short* idx = g_idx + (size_t)row * CAP;
        float s = 0.f;
        int base = 0;
        for (int k = 0; k < NN / 128; k++) {
            float4 a = Ar[k * 32 + lane];
            s += (a.x + a.y) + (a.z + a.w);
            bool any = (a.x != 0.f) | (a.y != 0.f) | (a.z != 0.f) | (a.w != 0.f);
            if (__ballot_sync(0xffffffffu, any) == 0u) continue;
            int col = (k * 32 + lane) * 4;
            unsigned m;
            m = __ballot_sync(0xffffffffu, a.x != 0.f);
            if (a.x != 0.f) { int p = base + __popc(m & lt); if (p < CAP) idx[p] = (unsigned short)col; }
            base += __popc(m);
            m = __ballot_sync(0xffffffffu, a.y != 0.f);
            if (a.y != 0.f) { int p = base + __popc(m & lt); if (p < CAP) idx[p] = (unsigned short)(col + 1); }
            base += __popc(m);
            m = __ballot_sync(0xffffffffu, a.z != 0.f);
            if (a.z != 0.f) { int p = base + __popc(m & lt); if (p < CAP) idx[p] = (unsigned short)(col + 2); }
            base += __popc(m);
            m = __ballot_sync(0xffffffffu, a.w != 0.f);
            if (a.w != 0.f) { int p = base + __popc(m & lt); if (p < CAP) idx[p] = (unsigned short)(col + 3); }
            base += __popc(m);
        }
        float t = s;
        #pragma unroll
        for (int o = 16; o; o >>= 1) t += __shfl_xor_sync(0xffffffffu, t, o);
        float d = rsqrtf(t + 1.f);        // all lanes hold the full sum after butterfly
        if (lane == 0) { g_cnt[row] = base; g_dinv[row] = d; }
        float4 v = ((const float4*)x)[(size_t)row * 32 + lane];
        v.x *= d; v.y *= d; v.z *= d; v.w *= d;
        ((float4*)g_xs)[(size_t)row * 32 + lane] = v;
    }
}

// ---------------- agg[b][i][:] = d_i * (xs[i] + sum_{j in idx} xs[j]) ----------------
__global__ void k_gather(const float* __restrict__ A) {
    int warp = (blockIdx.x * blockDim.x + threadIdx.x) >> 5;
    int lane = threadIdx.x & 31;
    const float4* xs4 = (const float4*)g_xs;
    size_t rowbase = (size_t)warp * 32;
    float4 acc = xs4[rowbase + lane];   // +I (diagonal) term: d_i x[i]
    int cnt = g_cnt[warp];
    size_t bb = ((size_t)(warp >> 12)) * NN * 32;   // batch base in float4s
    if (cnt <= CAP) {
        const unsigned short* idx = g_idx + (size_t)warp * CAP;
        int p = 0;
        while (p < cnt) {
            int jv = (p + lane < cnt) ? (int)idx[p + lane] : 0;
            int np = min(32, cnt - p);
            int q = 0;
            for (; q + 4 <= np; q += 4) {
                int j0 = __shfl_sync(0xffffffffu, jv, q);
                int j1 = __shfl_sync(0xffffffffu, jv, q + 1);
                int j2 = __shfl_sync(0xffffffffu, jv, q + 2);
                int j3 = __shfl_sync(0xffffffffu, jv, q + 3);
                float4 v0 = xs4[bb + (size_t)j0 * 32 + lane];
                float4 v1 = xs4[bb + (size_t)j1 * 32 + lane];
                float4 v2 = xs4[bb + (size_t)j2 * 32 + lane];
                float4 v3 = xs4[bb + (size_t)j3 * 32 + lane];
                acc.x += (v0.x + v1.x) + (v2.x + v3.x);
                acc.y += (v0.y + v1.y) + (v2.y + v3.y);
                acc.z += (v0.z + v1.z) + (v2.z + v3.z);
                acc.w += (v0.w + v1.w) + (v2.w + v3.w);
            }
            for (; q < np; q++) {
                int j = __shfl_sync(0xffffffffu, jv, q);
                float4 v = xs4[bb + (size_t)j * 32 + lane];
                acc.x += v.x; acc.y += v.y; acc.z += v.z; acc.w += v.w;
            }
            p += 32;
        }
    } else {
        const float* Ar = A + (size_t)warp * NN;
        for (int j0 = 0; j0 < NN; j0 += 32) {
            float a = Ar[j0 + lane];
            unsigned m = __ballot_sync(0xffffffffu, a != 0.f);
            while (m) {
                int q = __ffs(m) - 1; m &= m - 1;
                float4 v = xs4[bb + (size_t)(j0 + q) * 32 + lane];
                acc.x += v.x; acc.y += v.y; acc.z += v.z; acc.w += v.w;
            }
        }
    }
    float di = g_dinv[warp];
    acc.x *= di; acc.y *= di; acc.z *= di; acc.w *= di;
    ((float4*)g_agg)[rowbase + lane] = acc;
}

// ---- fused prologue: conv1d (8 channels/block) + zx GEMM, one kernel ----
// block = (b, o0): computes dyn[b][o0..o0+8][0..127] in smem, then
// zx[b][o0..o0+8][g] for all 512 gates.
__global__ void __launch_bounds__(512, 1) k_pro(const float* __restrict__ x,
                                                const float* __restrict__ cw,
                                                const float* __restrict__ cb,
                                                const float* __restrict__ wih,
                                                const float* __restrict__ bih,
                                                const float* __restrict__ bhh) {
    int b = blockIdx.x >> 4;
    int o0 = (blockIdx.x & 15) * 8;
    int tid = threadIdx.x;
    extern __shared__ float sm[];
    float* xw  = sm;                       // [128][130] padded, halo at 0 and 129
    float* wsh = sm + 128 * 130;           // [8][128][3]
    float* dsh = wsh + 8 * 128 * 3;        // [8][128]  (16B-aligned offset)

    // load x window (last 128 nodes) with zero halo
    const float* xb = x + ((size_t)b * NN + (NN - HID)) * HID;
    for (int idx = tid; idx < 128 * 128; idx += 512) {
        int i = idx >> 7, t = idx & 127;
        xw[i * 130 + 1 + t] = xb[(size_t)i * HID + t];
    }
    if (tid < 128) { xw[tid * 130] = 0.f; xw[tid * 130 + 129] = 0.f; }
    // load conv weights for this block's 8 output channels
    for (int idx = tid; idx < 8 * 128 * 3; idx += 512)
        wsh[idx] = cw[(size_t)(o0) * 128 * 3 + idx];
    __syncthreads();

    // conv: each thread does 2 (o_local, t) items
    #pragma unroll
    for (int s = 0; s < 2; s++) {
        int id = tid + s * 512;
        int ol = id >> 7, t = id & 127;
        float acc = cb[o0 + ol];
        const float* wrow = wsh + ol * 384;
        for (int i = 0; i < 128; i++) {
            float xm = xw[i * 130 + t];
            float x0 = xw[i * 130 + 1 + t];
            float xp = xw[i * 130 + 2 + t];
            acc += xm * wrow[i * 3] + x0 * wrow[i * 3 + 1] + xp * wrow[i * 3 + 2];
        }
        dsh[ol * 128 + t] = acc;
    }
    __syncthreads();

    // zx: g = tid (all 512 gates), 8 time rows (= the 8 channels just computed)
    int g = tid;
    const float4* dv4 = (const float4*)dsh;   // [tt][32]
    float acc[8];
    #pragma unroll
    for (int tt = 0; tt < 8; tt++) acc[tt] = 0.f;
    const float4* w4 = (const float4*)wih + g * 32;
    for (int c = 0; c < 4; c++) {
        float4 wv[8];
        #pragma unroll
        for (int j = 0; j < 8; j++) wv[j] = w4[c * 8 + j];
        #pragma unroll
        for (int tt = 0; tt < 8; tt++) {
            float s = 0.f;
            #pragma unroll
            for (int j = 0; j < 8; j++) {
                float4 dv = dv4[tt * 32 + c * 8 + j];
                s += wv[j].x * dv.x + wv[j].y * dv.y + wv[j].z * dv.z + wv[j].w * dv.w;
            }
            acc[tt] += s;
        }
    }
    float bias = bih[g] + bhh[g];
    for (int tt = 0; tt < 8; tt++) g_zx[(b * HID + o0 + tt) * G4 + g] = acc[tt] + bias;
}

// ---------------- LSTM: 2-CTA cluster per batch, weights in registers ----------------
__global__ void __launch_bounds__(512, 1) __cluster_dims__(2, 1, 1)
k_lstm(const float* __restrict__ whh) {
    int b = blockIdx.x >> 1;
    int r = blockIdx.x & 1;
    int tid = threadIdx.x;
    int lg = tid & 255;
    int hh = tid >> 8;
    int cls = lg >> 6;           // 0=i 1=f 2=g 3=o
    int kk = lg & 63;
    int gate = cls * 128 + 64 * r + kk;

    __shared__ float hbuf[2][HID];
    __shared__ float zA[256];
    __shared__ float zB[256];
    __shared__ __align__(8) unsigned int flg[2][2];   // [parity][epi-warp]

    ull w[32];
    const float4* w4 = (const float4*)whh + (size_t)gate * 32 + hh * 16;
    #pragma unroll
    for (int j = 0; j < 16; j++) {
        float4 v = w4[j];
        w[2 * j]     = pk(v.x, v.y);
        w[2 * j + 1] = pk(v.z, v.w);
    }
    if (tid < HID) { hbuf[0][tid] = 0.f; hbuf[1][tid] = 0.f; }
    if (tid < 4) ((unsigned int*)flg)[tid] = 0u;

    uint32_t lf0 = (uint32_t)__cvta_generic_to_shared(&flg[0][0]);
    uint32_t lf1 = (uint32_t)__cvta_generic_to_shared(&flg[1][0]);
    uint32_t ph0 = 0, ph1 = 0, pf0 = 0, pf1 = 0;
    if (tid < 64) {
        int hidx = 64 * r + tid;
        uint32_t a0 = (uint32_t)__cvta_generic_to_shared(&hbuf[0][hidx]);
        uint32_t a1 = (uint32_t)__cvta_generic_to_shared(&hbuf[1][hidx]);
        int wv = tid >> 5;
        uint32_t f0 = (uint32_t)__cvta_generic_to_shared(&flg[0][wv]);
        uint32_t f1 = (uint32_t)__cvta_generic_to_shared(&flg[1][wv]);
        asm("mapa.shared::cluster.u32 %0, %1, %2;" : "=r"(ph0) : "r"(a0), "r"(r ^ 1));
        asm("mapa.shared::cluster.u32 %0, %1, %2;" : "=r"(ph1) : "r"(a1), "r"(r ^ 1));
        asm("mapa.shared::cluster.u32 %0, %1, %2;" : "=r"(pf0) : "r"(f0), "r"(r ^ 1));
        asm("mapa.shared::cluster.u32 %0, %1, %2;" : "=r"(pf1) : "r"(f1), "r"(r ^ 1));
    }
    __syncthreads();
    asm volatile("barrier.cluster.arrive.aligned;" ::: "memory");
    asm volatile("barrier.cluster.wait.aligned;" ::: "memory");

    float c = 0.f;
    const float* zxp = g_zx + (size_t)b * HID * G4 + gate;
    float z0 = zxp[0];
    bool spinner = (hh != r);

    for (int step = 0; step < HID; step++) {
        if (spinner) {
            uint32_t fa = (step & 1) ? lf1 : lf0;
            ull v; unsigned lo, hi;
            do {
                asm volatile("ld.acquire.cluster.shared::cta.u64 %0, [%1];"
                             : "=l"(v) : "r"(fa) : "memory");
                lo = (unsigned)v; hi = (unsigned)(v >> 32);
            } while ((int)lo < step || (int)hi < step);
        }
        float znext = (step < HID - 1) ? zxp[(step + 1) * G4] : 0.f;
        const ulonglong2* h2 = (const ulonglong2*)(&hbuf[step & 1][hh * 64]);
        ull a0 = 0, a1 = 0, a2 = 0, a3 = 0;
        #pragma unroll
        for (int j = 0; j < 8; j++) {
            ulonglong2 hv0 = h2[2 * j];
            ulonglong2 hv1 = h2[2 * j + 1];
            fma2(a0, w[4 * j],     hv0.x);
            fma2(a1, w[4 * j + 1], hv0.y);
            fma2(a2, w[4 * j + 2], hv1.x);
            fma2(a3, w[4 * j + 3], hv1.y);
        }
        float2 s0 = unpk(a0), s1 = unpk(a1), s2 = unpk(a2), s3 = unpk(a3);
        float z = ((s0.x + s0.y) + (s1.x + s1.y)) + ((s2.x + s2.y) + (s3.x + s3.y));
        if (hh == 0) zA[lg] = z + z0;
        else         zB[lg] = z;
        z0 = znext;
        __syncthreads();
        int nxt = (step + 1) & 1;
        if (tid < 64) {
            float zi = zA[tid]       + zB[tid];
            float zf = zA[64 + tid]  + zB[64 + tid];
            float zg = zA[128 + tid] + zB[128 + tid];
            float zo = zA[192 + tid] + zB[192 + tid];
            float iv = sigf(zi);
            float fv = sigf(zf);
            float gv = tanh_fast(zg);
            float ov = sigf(zo);
            c = fv * c + iv * gv;
            float h = ov * tanh_fast(c);
            int hidx = 64 * r + tid;
            hbuf[nxt][hidx] = h;
            uint32_t pa = nxt ? ph1 : ph0;
            asm volatile("st.shared::cluster.f32 [%0], %1;" :: "r"(pa), "f"(h) : "memory");
            g_lwm[((size_t)b * HID + step) * HID + hidx] = h;
            __syncwarp();
            if ((tid & 31) == 0) {
                uint32_t fa = nxt ? pf1 : pf0;
                asm volatile("st.release.cluster.shared::cluster.u32 [%0], %1;"
                             :: "r"(fa), "r"(step + 1) : "memory");
            }
        }
        __syncthreads();
    }
    asm volatile("barrier.cluster.arrive.aligned;" ::: "memory");
    asm volatile("barrier.cluster.wait.aligned;" ::: "memory");
}

// ---------------- out[b][i][h] = sigmoid(agg[b][i] @ lw[b]) : 256 thr, 64 rows ----------------
__global__ void __launch_bounds__(256) k_out(float* __restrict__ out) {
    int b = blockIdx.x >> 6;
    int r0 = (blockIdx.x & 63) * 64;
    int h = threadIdx.x & 127;
    int rh = threadIdx.x >> 7;          // 0 or 1 -> row group
    __shared__ float4 as4[64 * 32];     // [r][f4]
    for (int i = threadIdx.x; i < 64 * 32; i += 256)
        as4[i] = ((const float4*)g_agg)[((size_t)b * NN + r0 + (i >> 5)) * 32 + (i & 31)];
    __syncthreads();
    const float4* my4 = as4 + rh * 32 * 32;
    float acc[32];
    #pragma unroll
    for (int r = 0; r < 32; r++) acc[r] = 0.f;
    for (int f4 = 0; f4 < 32; f4++) {
        float l0 = g_lwm[(b * HID + 4 * f4 + 0) * HID + h];
        float l1 = g_lwm[(b * HID + 4 * f4 + 1) * HID + h];
        float l2 = g_lwm[(b * HID + 4 * f4 + 2) * HID + h];
        float l3 = g_lwm[(b * HID + 4 * f4 + 3) * HID + h];
        #pragma unroll
        for (int r = 0; r < 32; r++) {
            float4 av = my4[r * 32 + f4];
            acc[r] += av.x * l0 + av.y * l1 + av.z * l2 + av.w * l3;
        }
    }
    for (int r = 0; r < 32; r++)
        out[((size_t)b * NN + r0 + rh * 32 + r) * HID + h] = sigf(acc[r]);
}

// ---------------- launch ----------------
extern "C" void kernel_launch(void* const* d_in, const int* in_sizes, int n_in,
                              void* d_out, int out_size) {
    const float* x   = (const float*)d_in[0];
    const float* A   = (const float*)d_in[1];
    const float* cw  = (const float*)d_in[2];
    const float* cb  = (const float*)d_in[3];
    const float* wih = (const float*)d_in[4];
    const float* whh = (const float*)d_in[5];
    const float* bih = (const float*)d_in[6];
    const float* bhh = (const float*)d_in[7];
    float* out = (float*)d_out;

    static cudaStream_t s2 = nullptr;
    static cudaEvent_t eF = nullptr, eJ = nullptr;
    if (!s2) {
        cudaStreamCreateWithFlags(&s2, cudaStreamNonBlocking);
        cudaEventCreateWithFlags(&eF, cudaEventDisableTiming);
        cudaEventCreateWithFlags(&eJ, cudaEventDisableTiming);
        cudaFuncSetAttribute(k_pro, cudaFuncAttributeMaxDynamicSharedMemorySize,
                             (128 * 130 + 8 * 128 * 3 + 8 * 128) * 4);
    }

    // fused LSTM prologue (conv + zx) uncontended on an empty chip
    k_pro<<<64, 512, (128 * 130 + 8 * 128 * 3 + 8 * 128) * 4>>>(x, cw, cb, wih, bih, bhh);

    // fork: lstm (main) first -> clusters claim SMs; bounded A-path on s2
    cudaEventRecord(eF, 0);
    cudaStreamWaitEvent(s2, eF, 0);
    k_lstm<<<2 * BATCH, 512>>>(whh);
    k_rowsum<<<RS_CTAS, RS_THREADS, 0, s2>>>(A, x);
    k_gather<<<BATCH * NN / 8, 256, 0, s2>>>(A);
    cudaEventRecord(eJ, s2);

    cudaStreamWaitEvent(0, eJ, 0);
    k_out<<<BATCH * (NN / 64), 256>>>(out);
}

// round 16
// speedup vs baseline: 1.0492x; 1.0492x over previous
#include <cuda_runtime.h>
#include <math.h>
#include <stdint.h>

#define BATCH 4
#define NN 4096
#define HID 128
#define G4 512
#define CAP 640
#define RS_CTAS 264
#define RS_THREADS 1024

typedef unsigned long long ull;

// ---------------- device scratch ----------------
__device__ float g_dinv[BATCH * NN];
__device__ int   g_cnt[BATCH * NN];
__device__ unsigned short g_idx[(size_t)BATCH * NN * CAP];   // ~21 MB
__device__ float g_zx[BATCH * HID * G4];                     // x-part of gates + biases
__device__ float g_lwm[BATCH * HID * HID];                   // lstm hidden [b][t][h]
__device__ float g_xs[(size_t)BATCH * NN * HID];             // d_j * x[b][j][:]
__device__ float g_agg[(size_t)BATCH * NN * HID];            // (A_norm @ x)[b][i][:]

__device__ __forceinline__ float sigf(float x) {
    return __fdividef(1.f, 1.f + __expf(-x));
}
// HW tanh (sm_75+): 1 MUFU op, err ~2^-11 — used only inside the LSTM recurrence
__device__ __forceinline__ float tanh_hw(float x) {
    float r; asm("tanh.approx.f32 %0, %1;" : "=f"(r) : "f"(x)); return r;
}
__device__ __forceinline__ float sig_hw(float x) {
    return fmaf(0.5f, tanh_hw(0.5f * x), 0.5f);
}
__device__ __forceinline__ void fma2(ull& d, ull a, ull b) {
    asm("fma.rn.f32x2 %0, %1, %2, %0;" : "+l"(d) : "l"(a), "l"(b));
}
__device__ __forceinline__ float2 unpk(ull v) {
    float2 r; asm("mov.b64 {%0,%1}, %2;" : "=f"(r.x), "=f"(r.y) : "l"(v)); return r;
}
__device__ __forceinline__ ull pk(float x, float y) {
    ull r; asm("mov.b64 %0, {%1,%2};" : "=l"(r) : "f"(x), "f"(y)); return r;
}

// ---- degree + sparse index build + fused x-scale: persistent, 264 CTAs (2/SM) ----
__global__ void __launch_bounds__(RS_THREADS, 2) k_rowsum(const float* __restrict__ A,
                                                          const float* __restrict__ x) {
    int gwarp = (blockIdx.x * RS_THREADS + threadIdx.x) >> 5;
    int lane = threadIdx.x & 31;
    unsigned lt = (1u << lane) - 1u;
    const int nwarp = RS_CTAS * (RS_THREADS / 32);
    for (int row = gwarp; row < BATCH * NN; row += nwarp) {
        const float4* Ar = (const float4*)(A + (size_t)row * NN);
        unsigned short* idx = g_idx + (size_t)row * CAP;
        float s = 0.f;
        int base = 0;
        for (int k = 0; k < NN / 128; k++) {
            float4 a = Ar[k * 32 + lane];
            s += (a.x + a.y) + (a.z + a.w);
            bool any = (a.x != 0.f) | (a.y != 0.f) | (a.z != 0.f) | (a.w != 0.f);
            if (__ballot_sync(0xffffffffu, any) == 0u) continue;
            int col = (k * 32 + lane) * 4;
            unsigned m;
            m = __ballot_sync(0xffffffffu, a.x != 0.f);
            if (a.x != 0.f) { int p = base + __popc(m & lt); if (p < CAP) idx[p] = (unsigned short)col; }
            base += __popc(m);
            m = __ballot_sync(0xffffffffu, a.y != 0.f);
            if (a.y != 0.f) { int p = base + __popc(m & lt); if (p < CAP) idx[p] = (unsigned short)(col + 1); }
            base += __popc(m);
            m = __ballot_sync(0xffffffffu, a.z != 0.f);
            if (a.z != 0.f) { int p = base + __popc(m & lt); if (p < CAP) idx[p] = (unsigned short)(col + 2); }
            base += __popc(m);
            m = __ballot_sync(0xffffffffu, a.w != 0.f);
            if (a.w != 0.f) { int p = base + __popc(m & lt); if (p < CAP) idx[p] = (unsigned short)(col + 3); }
            base += __popc(m);
        }
        float t = s;
        #pragma unroll
        for (int o = 16; o; o >>= 1) t += __shfl_xor_sync(0xffffffffu, t, o);
        float d = rsqrtf(t + 1.f);        // all lanes hold the full sum after butterfly
        if (lane == 0) { g_cnt[row] = base; g_dinv[row] = d; }
        float4 v = ((const float4*)x)[(size_t)row * 32 + lane];
        v.x *= d; v.y *= d; v.z *= d; v.w *= d;
        ((float4*)g_xs)[(size_t)row * 32 + lane] = v;
    }
}

// ---------------- agg[b][i][:] = d_i * (xs[i] + sum_{j in idx} xs[j]) ----------------
__global__ void k_gather(const float* __restrict__ A) {
    int warp = (blockIdx.x * blockDim.x + threadIdx.x) >> 5;
    int lane = threadIdx.x & 31;
    const float4* xs4 = (const float4*)g_xs;
    size_t rowbase = (size_t)warp * 32;
    float4 acc = xs4[rowbase + lane];   // +I (diagonal) term: d_i x[i]
    int cnt = g_cnt[warp];
    size_t bb = ((size_t)(warp >> 12)) * NN * 32;   // batch base in float4s
    if (cnt <= CAP) {
        const unsigned short* idx = g_idx + (size_t)warp * CAP;
        int p = 0;
        while (p < cnt) {
            int jv = (p + lane < cnt) ? (int)idx[p + lane] : 0;
            int np = min(32, cnt - p);
            int q = 0;
            for (; q + 4 <= np; q += 4) {
                int j0 = __shfl_sync(0xffffffffu, jv, q);
                int j1 = __shfl_sync(0xffffffffu, jv, q + 1);
                int j2 = __shfl_sync(0xffffffffu, jv, q + 2);
                int j3 = __shfl_sync(0xffffffffu, jv, q + 3);
                float4 v0 = xs4[bb + (size_t)j0 * 32 + lane];
                float4 v1 = xs4[bb + (size_t)j1 * 32 + lane];
                float4 v2 = xs4[bb + (size_t)j2 * 32 + lane];
                float4 v3 = xs4[bb + (size_t)j3 * 32 + lane];
                acc.x += (v0.x + v1.x) + (v2.x + v3.x);
                acc.y += (v0.y + v1.y) + (v2.y + v3.y);
                acc.z += (v0.z + v1.z) + (v2.z + v3.z);
                acc.w += (v0.w + v1.w) + (v2.w + v3.w);
            }
            for (; q < np; q++) {
                int j = __shfl_sync(0xffffffffu, jv, q);
                float4 v = xs4[bb + (size_t)j * 32 + lane];
                acc.x += v.x; acc.y += v.y; acc.z += v.z; acc.w += v.w;
            }
            p += 32;
        }
    } else {
        const float* Ar = A + (size_t)warp * NN;
        for (int j0 = 0; j0 < NN; j0 += 32) {
            float a = Ar[j0 + lane];
            unsigned m = __ballot_sync(0xffffffffu, a != 0.f);
            while (m) {
                int q = __ffs(m) - 1; m &= m - 1;
                float4 v = xs4[bb + (size_t)(j0 + q) * 32 + lane];
                acc.x += v.x; acc.y += v.y; acc.z += v.z; acc.w += v.w;
            }
        }
    }
    float di = g_dinv[warp];
    acc.x *= di; acc.y *= di; acc.z *= di; acc.w *= di;
    ((float4*)g_agg)[rowbase + lane] = acc;
}

// ---- fused prologue: conv1d (8 channels/block) + zx GEMM, one kernel ----
__global__ void __launch_bounds__(512, 1) k_pro(const float* __restrict__ x,
                                                const float* __restrict__ cw,
                                                const float* __restrict__ cb,
                                                const float* __restrict__ wih,
                                                const float* __restrict__ bih,
                                                const float* __restrict__ bhh) {
    int b = blockIdx.x >> 4;
    int o0 = (blockIdx.x & 15) * 8;
    int tid = threadIdx.x;
    extern __shared__ float sm[];
    float* xw  = sm;                       // [128][130] padded, halo at 0 and 129
    float* wsh = sm + 128 * 130;           // [8][128][3]
    float* dsh = wsh + 8 * 128 * 3;        // [8][128]

    const float* xb = x + ((size_t)b * NN + (NN - HID)) * HID;
    for (int idx = tid; idx < 128 * 128; idx += 512) {
        int i = idx >> 7, t = idx & 127;
        xw[i * 130 + 1 + t] = xb[(size_t)i * HID + t];
    }
    if (tid < 128) { xw[tid * 130] = 0.f; xw[tid * 130 + 129] = 0.f; }
    for (int idx = tid; idx < 8 * 128 * 3; idx += 512)
        wsh[idx] = cw[(size_t)(o0) * 128 * 3 + idx];
    __syncthreads();

    #pragma unroll
    for (int s = 0; s < 2; s++) {
        int id = tid + s * 512;
        int ol = id >> 7, t = id & 127;
        float acc = cb[o0 + ol];
        const float* wrow = wsh + ol * 384;
        for (int i = 0; i < 128; i++) {
            float xm = xw[i * 130 + t];
            float x0 = xw[i * 130 + 1 + t];
            float xp = xw[i * 130 + 2 + t];
            acc += xm * wrow[i * 3] + x0 * wrow[i * 3 + 1] + xp * wrow[i * 3 + 2];
        }
        dsh[ol * 128 + t] = acc;
    }
    __syncthreads();

    int g = tid;
    const float4* dv4 = (const float4*)dsh;   // [tt][32]
    float acc[8];
    #pragma unroll
    for (int tt = 0; tt < 8; tt++) acc[tt] = 0.f;
    const float4* w4 = (const float4*)wih + g * 32;
    for (int c = 0; c < 4; c++) {
        float4 wv[8];
        #pragma unroll
        for (int j = 0; j < 8; j++) wv[j] = w4[c * 8 + j];
        #pragma unroll
        for (int tt = 0; tt < 8; tt++) {
            float s = 0.f;
            #pragma unroll
            for (int j = 0; j < 8; j++) {
                float4 dv = dv4[tt * 32 + c * 8 + j];
                s += wv[j].x * dv.x + wv[j].y * dv.y + wv[j].z * dv.z + wv[j].w * dv.w;
            }
            acc[tt] += s;
        }
    }
    float bias = bih[g] + bhh[g];
    for (int tt = 0; tt < 8; tt++) g_zx[(b * HID + o0 + tt) * G4 + g] = acc[tt] + bias;
}

// ---------------- LSTM: 2-CTA cluster per batch, weights in registers ----------------
__global__ void __launch_bounds__(512, 1) __cluster_dims__(2, 1, 1)
k_lstm(const float* __restrict__ whh) {
    int b = blockIdx.x >> 1;
    int r = blockIdx.x & 1;
    int tid = threadIdx.x;
    int lg = tid & 255;
    int hh = tid >> 8;
    int cls = lg >> 6;           // 0=i 1=f 2=g 3=o
    int kk = lg & 63;
    int gate = cls * 128 + 64 * r + kk;

    __shared__ float hbuf[2][HID];
    __shared__ float zA[256];
    __shared__ float zB[256];
    __shared__ __align__(8) unsigned int flg[2][2];   // [parity][epi-warp]

    ull w[32];
    const float4* w4 = (const float4*)whh + (size_t)gate * 32 + hh * 16;
    #pragma unroll
    for (int j = 0; j < 16; j++) {
        float4 v = w4[j];
        w[2 * j]     = pk(v.x, v.y);
        w[2 * j + 1] = pk(v.z, v.w);
    }
    if (tid < HID) { hbuf[0][tid] = 0.f; hbuf[1][tid] = 0.f; }
    if (tid < 4) ((unsigned int*)flg)[tid] = 0u;

    uint32_t lf0 = (uint32_t)__cvta_generic_to_shared(&flg[0][0]);
    uint32_t lf1 = (uint32_t)__cvta_generic_to_shared(&flg[1][0]);
    uint32_t ph0 = 0, ph1 = 0, pf0 = 0, pf1 = 0;
    if (tid < 64) {
        int hidx = 64 * r + tid;
        uint32_t a0 = (uint32_t)__cvta_generic_to_shared(&hbuf[0][hidx]);
        uint32_t a1 = (uint32_t)__cvta_generic_to_shared(&hbuf[1][hidx]);
        int wv = tid >> 5;
        uint32_t f0 = (uint32_t)__cvta_generic_to_shared(&flg[0][wv]);
        uint32_t f1 = (uint32_t)__cvta_generic_to_shared(&flg[1][wv]);
        asm("mapa.shared::cluster.u32 %0, %1, %2;" : "=r"(ph0) : "r"(a0), "r"(r ^ 1));
        asm("mapa.shared::cluster.u32 %0, %1, %2;" : "=r"(ph1) : "r"(a1), "r"(r ^ 1));
        asm("mapa.shared::cluster.u32 %0, %1, %2;" : "=r"(pf0) : "r"(f0), "r"(r ^ 1));
        asm("mapa.shared::cluster.u32 %0, %1, %2;" : "=r"(pf1) : "r"(f1), "r"(r ^ 1));
    }
    __syncthreads();
    asm volatile("barrier.cluster.arrive.aligned;" ::: "memory");
    asm volatile("barrier.cluster.wait.aligned;" ::: "memory");

    float c = 0.f;
    const float* zxp = g_zx + (size_t)b * HID * G4 + gate;
    float z0 = zxp[0];
    bool spinner = (hh != r);

    for (int step = 0; step < HID; step++) {
        if (spinner) {
            uint32_t fa = (step & 1) ? lf1 : lf0;
            ull v; unsigned lo, hi;
            do {
                asm volatile("ld.acquire.cluster.shared::cta.u64 %0, [%1];"
                             : "=l"(v) : "r"(fa) : "memory");
                lo = (unsigned)v; hi = (unsigned)(v >> 32);
            } while ((int)lo < step || (int)hi < step);
        }
        float znext = (step < HID - 1) ? zxp[(step + 1) * G4] : 0.f;
        const ulonglong2* h2 = (const ulonglong2*)(&hbuf[step & 1][hh * 64]);
        ull a0 = 0, a1 = 0, a2 = 0, a3 = 0;
        #pragma unroll
        for (int j = 0; j < 8; j++) {
            ulonglong2 hv0 = h2[2 * j];
            ulonglong2 hv1 = h2[2 * j + 1];
            fma2(a0, w[4 * j],     hv0.x);
            fma2(a1, w[4 * j + 1], hv0.y);
            fma2(a2, w[4 * j + 2], hv1.x);
            fma2(a3, w[4 * j + 3], hv1.y);
        }
        float2 s0 = unpk(a0), s1 = unpk(a1), s2 = unpk(a2), s3 = unpk(a3);
        float z = ((s0.x + s0.y) + (s1.x + s1.y)) + ((s2.x + s2.y) + (s3.x + s3.y));
        if (hh == 0) zA[lg] = z + z0;
        else         zB[lg] = z;
        z0 = znext;
        __syncthreads();
        int nxt = (step + 1) & 1;
        if (tid < 64) {
            float zi = zA[tid]       + zB[tid];
            float zf = zA[64 + tid]  + zB[64 + tid];
            float zg = zA[128 + tid] + zB[128 + tid];
            float zo = zA[192 + tid] + zB[192 + tid];
            float iv = sig_hw(zi);
            float fv = sig_hw(zf);
            float gv = tanh_hw(zg);
            float ov = sig_hw(zo);
            c = fv * c + iv * gv;
            float h = ov * tanh_hw(c);
            int hidx = 64 * r + tid;
            hbuf[nxt][hidx] = h;
            uint32_t pa = nxt ? ph1 : ph0;
            asm volatile("st.shared::cluster.f32 [%0], %1;" :: "r"(pa), "f"(h) : "memory");
            g_lwm[((size_t)b * HID + step) * HID + hidx] = h;
            __syncwarp();
            if ((tid & 31) == 0) {
                uint32_t fa = nxt ? pf1 : pf0;
                asm volatile("st.release.cluster.shared::cluster.u32 [%0], %1;"
                             :: "r"(fa), "r"(step + 1) : "memory");
            }
        }
        __syncthreads();
    }
    asm volatile("barrier.cluster.arrive.aligned;" ::: "memory");
    asm volatile("barrier.cluster.wait.aligned;" ::: "memory");
}

// ---------------- out[b][i][h] = sigmoid(agg[b][i] @ lw[b]) : 256 thr, 64 rows ----------------
__global__ void __launch_bounds__(256) k_out(float* __restrict__ out) {
    int b = blockIdx.x >> 6;
    int r0 = (blockIdx.x & 63) * 64;
    int h = threadIdx.x & 127;
    int rh = threadIdx.x >> 7;          // 0 or 1 -> row group
    __shared__ float4 as4[64 * 32];     // [r][f4]
    for (int i = threadIdx.x; i < 64 * 32; i += 256)
        as4[i] = ((const float4*)g_agg)[((size_t)b * NN + r0 + (i >> 5)) * 32 + (i & 31)];
    __syncthreads();
    const float4* my4 = as4 + rh * 32 * 32;
    float acc[32];
    #pragma unroll
    for (int r = 0; r < 32; r++) acc[r] = 0.f;
    for (int f4 = 0; f4 < 32; f4++) {
        float l0 = g_lwm[(b * HID + 4 * f4 + 0) * HID + h];
        float l1 = g_lwm[(b * HID + 4 * f4 + 1) * HID + h];
        float l2 = g_lwm[(b * HID + 4 * f4 + 2) * HID + h];
        float l3 = g_lwm[(b * HID + 4 * f4 + 3) * HID + h];
        #pragma unroll
        for (int r = 0; r < 32; r++) {
            float4 av = my4[r * 32 + f4];
            acc[r] += av.x * l0 + av.y * l1 + av.z * l2 + av.w * l3;
        }
    }
    for (int r = 0; r < 32; r++)
        out[((size_t)b * NN + r0 + rh * 32 + r) * HID + h] = sigf(acc[r]);
}

// ---------------- launch ----------------
extern "C" void kernel_launch(void* const* d_in, const int* in_sizes, int n_in,
                              void* d_out, int out_size) {
    const float* x   = (const float*)d_in[0];
    const float* A   = (const float*)d_in[1];
    const float* cw  = (const float*)d_in[2];
    const float* cb  = (const float*)d_in[3];
    const float* wih = (const float*)d_in[4];
    const float* whh = (const float*)d_in[5];
    const float* bih = (const float*)d_in[6];
    const float* bhh = (const float*)d_in[7];
    float* out = (float*)d_out;

    static cudaStream_t s2 = nullptr;
    static cudaEvent_t eF = nullptr, eJ = nullptr;
    if (!s2) {
        cudaStreamCreateWithFlags(&s2, cudaStreamNonBlocking);
        cudaEventCreateWithFlags(&eF, cudaEventDisableTiming);
        cudaEventCreateWithFlags(&eJ, cudaEventDisableTiming);
        cudaFuncSetAttribute(k_pro, cudaFuncAttributeMaxDynamicSharedMemorySize,
                             (128 * 130 + 8 * 128 * 3 + 8 * 128) * 4);
    }

    // fused LSTM prologue (conv + zx) uncontended on an empty chip
    k_pro<<<64, 512, (128 * 130 + 8 * 128 * 3 + 8 * 128) * 4>>>(x, cw, cb, wih, bih, bhh);

    // fork: lstm (main) first -> clusters claim SMs; bounded A-path on s2
    cudaEventRecord(eF, 0);
    cudaStreamWaitEvent(s2, eF, 0);
    k_lstm<<<2 * BATCH, 512>>>(whh);
    k_rowsum<<<RS_CTAS, RS_THREADS, 0, s2>>>(A, x);
    k_gather<<<BATCH * NN / 8, 256, 0, s2>>>(A);
    cudaEventRecord(eJ, s2);

    cudaStreamWaitEvent(0, eJ, 0);
    k_out<<<BATCH * (NN / 64), 256>>>(out);
}